// round 14
// baseline (speedup 1.0000x reference)
#include <cuda_runtime.h>
#include <cuda_bf16.h>
#include <math_constants.h>

// Problem constants (fixed by setup_inputs)
#define Bq 4
#define Hq 8
#define BH 32          // B*H
#define Lq 2048
#define Dq 64
#define SK 40          // sample_k
#define NT 40          // n_top
#define NS 32          // key splits in flash kernel (64 keys each)
#define SCALE 0.125f   // 1/sqrt(64)

// ---------------- scratch (device globals; no allocation) ----------------
__device__ float g_M[BH * Lq];                 // 256 KB
__device__ int   g_top[BH * NT];               // 5 KB
__device__ float g_vmean[BH * Dq];             // 8 KB
__device__ float g_pm[NS * BH * NT];           // per-split row max
__device__ float g_psum[NS * BH * NT];         // per-split exp-sum
__device__ float g_part[(size_t)NS * BH * NT * Dq];  // 10.5 MB partial ctx

// Fast exp on the FMA pipe: exp(x) = 2^(x*log2e), deg-6 poly + exponent bits.
__device__ __forceinline__ float fexpf(float x) {
    float y = x * 1.4426950408889634f;
    y = fmaxf(y, -125.0f);
    float r = rintf(y);
    float f = y - r;
    float p = 1.5403530e-4f;
    p = fmaf(p, f, 1.3333558e-3f);
    p = fmaf(p, f, 9.6181291e-3f);
    p = fmaf(p, f, 5.5504109e-2f);
    p = fmaf(p, f, 2.4022651e-1f);
    p = fmaf(p, f, 6.9314718e-1f);
    p = fmaf(p, f, 1.0f);
    return p * __int_as_float(((int)r + 127) << 23);
}

// ---------------- kernel 1: M[bh,l] = max_s q.k - sum_s/L ----------------
template<int O, int V>
__device__ __forceinline__ void fold(float* p, int lane) {
    bool hi = (lane & O) != 0;
    #pragma unroll
    for (int j = 0; j < V / 2; j++) {
        float send = hi ? p[j] : p[j + V / 2];
        float keep = hi ? p[j + V / 2] : p[j];
        p[j] = keep + __shfl_xor_sync(0xffffffffu, send, O);
    }
}

__device__ __forceinline__ float dot16(const float* __restrict__ Kb, float2 q,
                                       int e, int base, int lane) {
    float p[16];
    #pragma unroll
    for (int j = 0; j < 16; j++) {
        int idx = __shfl_sync(0xffffffffu, e, base + j);
        float2 k = ((const float2*)(Kb + (size_t)idx * Dq))[lane];
        p[j] = q.x * k.x + q.y * k.y;
    }
    fold<16, 16>(p, lane);
    fold<8, 8>(p, lane);
    fold<4, 4>(p, lane);
    fold<2, 2>(p, lane);
    p[0] += __shfl_xor_sync(0xffffffffu, p[0], 1);
    return p[0];
}

__device__ __forceinline__ float dot8(const float* __restrict__ Kb, float2 q,
                                      int e, int lane) {
    float p[8];
    #pragma unroll
    for (int j = 0; j < 8; j++) {
        int idx = __shfl_sync(0xffffffffu, e, j);
        float2 k = ((const float2*)(Kb + (size_t)idx * Dq))[lane];
        p[j] = q.x * k.x + q.y * k.y;
    }
    fold<16, 8>(p, lane);
    fold<8, 4>(p, lane);
    fold<4, 2>(p, lane);
    p[0] += __shfl_xor_sync(0xffffffffu, p[0], 2);
    p[0] += __shfl_xor_sync(0xffffffffu, p[0], 1);
    return p[0];
}

__global__ void k_M(const float* __restrict__ Q, const float* __restrict__ K,
                    const int* __restrict__ idxs) {
    int w = blockIdx.x * 8 + (threadIdx.x >> 5);   // query id (bh*2048 + l)
    int lane = threadIdx.x & 31;
    int bh = w >> 11;
    int l  = w & (Lq - 1);
    float2 q = ((const float2*)(Q + (size_t)w * Dq))[lane];
    const float* Kb = K + (size_t)bh * Lq * Dq;
    int e0 = idxs[l * SK + lane];
    int e1 = (lane < 8) ? idxs[l * SK + 32 + lane] : 0;

    float a = dot16(Kb, q, e0, 0, lane);
    float b = dot16(Kb, q, e0, 16, lane);
    float c = dot8(Kb, q, e1, lane);

    float mx = fmaxf(fmaxf(a, b), c);
    float sm = 0.5f * (a + b) + 0.25f * c;
    #pragma unroll
    for (int o = 16; o; o >>= 1) {
        mx = fmaxf(mx, __shfl_xor_sync(0xffffffffu, mx, o));
        sm += __shfl_xor_sync(0xffffffffu, sm, o);
    }
    if (lane == 0) g_M[w] = mx - sm * (1.0f / (float)Lq);
}

// ---------------- kernel 2: top-40 per (b,h), 4-level radix select -------
__global__ void k_topk() {
    __shared__ int hist[8][256];
    __shared__ int suf[257];
    __shared__ int wred[8];
    __shared__ int s_T, s_cnt, s_min;
    int bh = blockIdx.x;
    int t = threadIdx.x, lane = t & 31, w = t >> 5;

    unsigned key[8];
    #pragma unroll
    for (int j = 0; j < 8; j++) {
        unsigned u = __float_as_uint(g_M[bh * Lq + t * 8 + j]);
        key[j] = (u & 0x80000000u) ? ~u : (u | 0x80000000u);
    }
    unsigned prefix = 0;
    int need = NT;
    if (t == 0) s_cnt = 0;

    #pragma unroll
    for (int level = 0; level < 4; level++) {
        int shift = 24 - 8 * level;
        for (int b = t; b < 8 * 256; b += 256) (&hist[0][0])[b] = 0;
        __syncthreads();
        #pragma unroll
        for (int j = 0; j < 8; j++) {
            bool match = (level == 0) || ((key[j] >> (shift + 8)) == prefix);
            if (match) atomicAdd(&hist[w][(key[j] >> shift) & 255u], 1);
        }
        __syncthreads();
        int h = 0;
        #pragma unroll
        for (int ww = 0; ww < 8; ww++) h += hist[ww][t];
        int sv = h;
        #pragma unroll
        for (int off = 1; off < 32; off <<= 1) {
            int v = __shfl_down_sync(0xffffffffu, sv, off);
            if (lane + off < 32) sv += v;
        }
        int wtot = __shfl_sync(0xffffffffu, sv, 0);
        if (lane == 0) wred[w] = wtot;
        __syncthreads();
        int higher = 0;
        #pragma unroll
        for (int ww = 0; ww < 8; ww++) if (ww > w) higher += wred[ww];
        suf[t] = sv + higher;
        if (t == 0) suf[256] = 0;
        __syncthreads();
        if (suf[t] >= need && suf[t + 1] < need) s_T = t;
        __syncthreads();
        int T = s_T;
        #pragma unroll
        for (int j = 0; j < 8; j++) {
            bool match = (level == 0) || ((key[j] >> (shift + 8)) == prefix);
            if (match && (int)((key[j] >> shift) & 255u) > T) {
                int p = atomicAdd(&s_cnt, 1);
                g_top[bh * NT + p] = t * 8 + j;
            }
        }
        need -= suf[T + 1];
        prefix = (prefix << 8) | (unsigned)T;
        __syncthreads();
    }

    for (int it = 0; it < need; it++) {
        int mi = Lq;
        #pragma unroll
        for (int j = 0; j < 8; j++)
            if (key[j] == prefix) mi = min(mi, t * 8 + j);
        #pragma unroll
        for (int off = 16; off; off >>= 1)
            mi = min(mi, __shfl_xor_sync(0xffffffffu, mi, off));
        if (lane == 0) wred[w] = mi;
        __syncthreads();
        if (t == 0) {
            int m = wred[0];
            #pragma unroll
            for (int ww = 1; ww < 8; ww++) m = min(m, wred[ww]);
            s_min = m;
            g_top[bh * NT + (NT - need) + it] = m;
        }
        __syncthreads();
        int m = s_min;
        if (m >= t * 8 && m < t * 8 + 8) key[m - t * 8] = 0u;
        __syncthreads();
    }
}

// ---------------- kernel 3: V mean over L per (b,h), float4 --------------
__global__ void k_vmean(const float* __restrict__ V) {
    __shared__ float4 ps[256];
    int bh = blockIdx.x;
    int t = threadIdx.x;
    int d4 = t & 15, part = t >> 4;
    const float4* Vb = (const float4*)(V + (size_t)bh * Lq * Dq);
    float4 s = make_float4(0.f, 0.f, 0.f, 0.f);
    int k0 = part * 128;
    for (int k = k0; k < k0 + 128; k++) {
        float4 v = Vb[(size_t)k * 16 + d4];
        s.x += v.x; s.y += v.y; s.z += v.z; s.w += v.w;
    }
    ps[t] = s;
    __syncthreads();
    if (t < 16) {
        float4 a = ps[t];
        #pragma unroll
        for (int pI = 1; pI < 16; pI++) {
            float4 v = ps[pI * 16 + t];
            a.x += v.x; a.y += v.y; a.z += v.z; a.w += v.w;
        }
        const float inv = 1.0f / (float)Lq;
        a.x *= inv; a.y *= inv; a.z *= inv; a.w *= inv;
        ((float4*)g_vmean)[bh * 16 + t] = a;
    }
}

// ---------------- kernel 4: broadcast V_mean (4 stores/thread) -----------
__global__ void k_fill(float4* __restrict__ out4) {
    int base = blockIdx.x * 1024 + threadIdx.x;   // 1024 blocks x 256 thr x 4
    #pragma unroll
    for (int r = 0; r < 4; r++) {
        int i = base + r * 256;
        out4[i] = ((const float4*)g_vmean)[(((i >> 15)) << 4) | (i & 15)];
    }
}

// ---------------- kernel 5: fused flash attention over 64-key split ------
// grid = BH*NS = 1024 blocks, 512 threads (16 warps), 3 blocks/SM -> 48
// resident warps. Warp (qg, half): GEMM1 computes 5 queries x 32 keys
// (lane = 1 key); GEMM2 computes 5 queries x 32 dims (lane = 1 dim).
// Row softmax stats combined across the 2 key-half warps via smem.
__global__ void __launch_bounds__(512, 3)
k_flash(const float* __restrict__ Q,
        const float* __restrict__ K,
        const float* __restrict__ V) {
    __shared__ float qs[NT * Dq];      // 10 KB
    __shared__ float Kt[Dq * 66];      // 16.5 KB transposed [d][k]; reused as P
    __shared__ float Vs[64 * Dq];      // 16 KB
    __shared__ float marr[8][2][5];
    __shared__ float sarr[8][2][5];
    __shared__ int stop[NT];
    int bh = blockIdx.x >> 5;
    int ks = blockIdx.x & 31;
    int t = threadIdx.x;               // 512
    const float* Qb = Q + (size_t)bh * Lq * Dq;
    const float* Kb = K + (size_t)bh * Lq * Dq;
    const float* Vb = V + (size_t)bh * Lq * Dq;
    if (t < NT) stop[t] = g_top[bh * NT + t];
    __syncthreads();
    for (int j = t; j < NT * Dq; j += 512) {
        int u = j >> 6, d = j & 63;
        qs[j] = Qb[(size_t)stop[u] * Dq + d];
    }
    for (int j = t; j < 64 * Dq; j += 512) {
        int r = j >> 6, d = j & 63;
        Kt[d * 66 + r] = Kb[(size_t)(ks * 64 + r) * Dq + d];
    }
    for (int j = t; j < 64 * Dq; j += 512) Vs[j] = Vb[(size_t)ks * 64 * Dq + j];
    __syncthreads();

    int w = t >> 5, lane = t & 31;
    int qg = w >> 1;                   // 0..7: queries qg*5..+4
    int half = w & 1;                  // key/dim half
    int kidx = half * 32 + lane;       // this lane's key (GEMM1) / dim (GEMM2)

    // GEMM1: acc[i] = q[qg*5+i] . K[kidx]
    float acc[5] = {};
    #pragma unroll
    for (int dc = 0; dc < Dq; dc += 4) {
        float4 a[5];
        #pragma unroll
        for (int i = 0; i < 5; i++)
            a[i] = *(const float4*)&qs[(qg * 5 + i) * Dq + dc];
        float b0 = Kt[(dc + 0) * 66 + kidx];
        float b1 = Kt[(dc + 1) * 66 + kidx];
        float b2 = Kt[(dc + 2) * 66 + kidx];
        float b3 = Kt[(dc + 3) * 66 + kidx];
        #pragma unroll
        for (int i = 0; i < 5; i++) {
            acc[i] = fmaf(a[i].x, b0, acc[i]);
            acc[i] = fmaf(a[i].y, b1, acc[i]);
            acc[i] = fmaf(a[i].z, b2, acc[i]);
            acc[i] = fmaf(a[i].w, b3, acc[i]);
        }
    }
    // warp-local row max over this half's 32 keys (batched butterflies)
    float m[5];
    #pragma unroll
    for (int i = 0; i < 5; i++) { acc[i] *= SCALE; m[i] = acc[i]; }
    #pragma unroll
    for (int o = 16; o; o >>= 1) {
        #pragma unroll
        for (int i = 0; i < 5; i++)
            m[i] = fmaxf(m[i], __shfl_xor_sync(0xffffffffu, m[i], o));
    }
    if (lane == 0) {
        #pragma unroll
        for (int i = 0; i < 5; i++) marr[qg][half][i] = m[i];
    }
    __syncthreads();
    #pragma unroll
    for (int i = 0; i < 5; i++)
        m[i] = fmaxf(marr[qg][0][i], marr[qg][1][i]);   // full-row max
    // exp + warp-local sum
    float s[5];
    #pragma unroll
    for (int i = 0; i < 5; i++) { acc[i] = fexpf(acc[i] - m[i]); s[i] = acc[i]; }
    #pragma unroll
    for (int o = 16; o; o >>= 1) {
        #pragma unroll
        for (int i = 0; i < 5; i++)
            s[i] += __shfl_xor_sync(0xffffffffu, s[i], o);
    }
    if (lane == 0) {
        #pragma unroll
        for (int i = 0; i < 5; i++) sarr[qg][half][i] = s[i];
    }
    __syncthreads();                    // also: all GEMM1 Kt reads done
    float* P = Kt;                      // reuse (40*64 = 2560 floats fit)
    #pragma unroll
    for (int i = 0; i < 5; i++)
        P[(qg * 5 + i) * 64 + kidx] = acc[i];
    if (lane == 0 && half == 0) {
        int sb = (bh * NS + ks) * NT + qg * 5;
        #pragma unroll
        for (int i = 0; i < 5; i++) {
            g_pm[sb + i] = m[i];
            g_psum[sb + i] = sarr[qg][0][i] + sarr[qg][1][i];
        }
    }
    __syncthreads();

    // GEMM2: ctx[i][kidx] = sum_k P[qg*5+i][k] * Vs[k][kidx]
    float c[5] = {};
    #pragma unroll
    for (int kk = 0; kk < 64; kk += 4) {
        float4 a[5];
        #pragma unroll
        for (int i = 0; i < 5; i++)
            a[i] = *(const float4*)&P[(qg * 5 + i) * 64 + kk];
        float v0 = Vs[(kk + 0) * Dq + kidx];
        float v1 = Vs[(kk + 1) * Dq + kidx];
        float v2 = Vs[(kk + 2) * Dq + kidx];
        float v3 = Vs[(kk + 3) * Dq + kidx];
        #pragma unroll
        for (int i = 0; i < 5; i++) {
            c[i] = fmaf(a[i].x, v0, c[i]);
            c[i] = fmaf(a[i].y, v1, c[i]);
            c[i] = fmaf(a[i].z, v2, c[i]);
            c[i] = fmaf(a[i].w, v3, c[i]);
        }
    }
    #pragma unroll
    for (int i = 0; i < 5; i++)
        g_part[((size_t)(ks * BH + bh) * NT + qg * 5 + i) * Dq + kidx] = c[i];
}

// ---------------- kernel 6: combine splits + scatter ---------------------
__global__ void k_comb(float* __restrict__ out) {
    int i = blockIdx.x * 256 + threadIdx.x;   // BH*NT*Dq = 81920
    if (i >= BH * NT * Dq) return;
    int d = i & 63;
    int r = i >> 6;
    int u = r % NT;
    int bh = r / NT;
    float M = -CUDART_INF_F;
    #pragma unroll 8
    for (int s = 0; s < NS; s++)
        M = fmaxf(M, g_pm[(bh * NS + s) * NT + u]);
    float sum = 0.f, ctx = 0.f;
    #pragma unroll 4
    for (int s = 0; s < NS; s++) {
        float wgt = fexpf(g_pm[(bh * NS + s) * NT + u] - M);
        sum = fmaf(g_psum[(bh * NS + s) * NT + u], wgt, sum);
        ctx = fmaf(g_part[((size_t)(s * BH + bh) * NT + u) * Dq + d], wgt, ctx);
    }
    int qi = g_top[bh * NT + u];
    out[((size_t)bh * Lq + qi) * Dq + d] = ctx / sum;
}

// ---------------- launch ---------------------------------------------------
extern "C" void kernel_launch(void* const* d_in, const int* in_sizes, int n_in,
                              void* d_out, int out_size) {
    const float* Q = (const float*)d_in[0];
    const float* K = (const float*)d_in[1];
    const float* V = (const float*)d_in[2];
    const int* idxs = (const int*)d_in[3];
    float* out = (float*)d_out;

    // order: k_flash is user launch #4 (profiled).
    k_vmean<<<BH, 256>>>(V);                                  // 1
    k_M<<<(BH * Lq) / 8, 256>>>(Q, K, idxs);                  // 2
    k_topk<<<BH, 256>>>();                                    // 3
    k_flash<<<BH * NS, 512>>>(Q, K, V);                       // 4  <-- profiled
    k_fill<<<(BH * Lq * Dq / 4) / 1024, 256>>>((float4*)out); // 5
    k_comb<<<(BH * NT * Dq + 255) / 256, 256>>>(out);         // 6
}

// round 15
// speedup vs baseline: 1.0886x; 1.0886x over previous
#include <cuda_runtime.h>
#include <cuda_bf16.h>
#include <math_constants.h>

// Problem constants (fixed by setup_inputs)
#define Bq 4
#define Hq 8
#define BH 32          // B*H
#define Lq 2048
#define Dq 64
#define SK 40          // sample_k
#define NT 40          // n_top
#define SCALE 0.125f   // 1/sqrt(64), exact power of two

// ---------------- scratch (device globals; no allocation) ----------------
__device__ float g_M[BH * Lq];                 // 256 KB
__device__ int   g_top[BH * NT];               // 5 KB
__device__ float g_qtop[BH * NT * Dq];         // compact scaled Q_top (328 KB)
__device__ float g_vmean[BH * Dq];             // 8 KB
__device__ float g_inv[BH * NT];               // per-row 1/softmax_sum
__device__ float g_scores[(size_t)BH * NT * Lq];   // 10.5 MB
__device__ float g_part[8 * BH * NT * Dq];     // 2.6 MB (k-split partials)

// Fast exp on the FMA pipe: exp(x) = 2^(x*log2e), deg-6 poly + exponent bits.
__device__ __forceinline__ float fexpf(float x) {
    float y = x * 1.4426950408889634f;
    y = fmaxf(y, -125.0f);
    float r = rintf(y);
    float f = y - r;
    float p = 1.5403530e-4f;
    p = fmaf(p, f, 1.3333558e-3f);
    p = fmaf(p, f, 9.6181291e-3f);
    p = fmaf(p, f, 5.5504109e-2f);
    p = fmaf(p, f, 2.4022651e-1f);
    p = fmaf(p, f, 6.9314718e-1f);
    p = fmaf(p, f, 1.0f);
    return p * __int_as_float(((int)r + 127) << 23);
}

// ---------------- kernel 1: M[bh,l] = max_s q.k - sum_s/L ----------------
template<int O, int V>
__device__ __forceinline__ void fold(float* p, int lane) {
    bool hi = (lane & O) != 0;
    #pragma unroll
    for (int j = 0; j < V / 2; j++) {
        float send = hi ? p[j] : p[j + V / 2];
        float keep = hi ? p[j + V / 2] : p[j];
        p[j] = keep + __shfl_xor_sync(0xffffffffu, send, O);
    }
}

__device__ __forceinline__ float dot16(const float* __restrict__ Kb, float2 q,
                                       int e, int base, int lane) {
    float p[16];
    #pragma unroll
    for (int j = 0; j < 16; j++) {
        int idx = __shfl_sync(0xffffffffu, e, base + j);
        float2 k = ((const float2*)(Kb + (size_t)idx * Dq))[lane];
        p[j] = q.x * k.x + q.y * k.y;
    }
    fold<16, 16>(p, lane);
    fold<8, 8>(p, lane);
    fold<4, 4>(p, lane);
    fold<2, 2>(p, lane);
    p[0] += __shfl_xor_sync(0xffffffffu, p[0], 1);
    return p[0];
}

__device__ __forceinline__ float dot8(const float* __restrict__ Kb, float2 q,
                                      int e, int lane) {
    float p[8];
    #pragma unroll
    for (int j = 0; j < 8; j++) {
        int idx = __shfl_sync(0xffffffffu, e, j);
        float2 k = ((const float2*)(Kb + (size_t)idx * Dq))[lane];
        p[j] = q.x * k.x + q.y * k.y;
    }
    fold<16, 8>(p, lane);
    fold<8, 4>(p, lane);
    fold<4, 2>(p, lane);
    p[0] += __shfl_xor_sync(0xffffffffu, p[0], 2);
    p[0] += __shfl_xor_sync(0xffffffffu, p[0], 1);
    return p[0];
}

__global__ void k_M(const float* __restrict__ Q, const float* __restrict__ K,
                    const int* __restrict__ idxs) {
    int w = blockIdx.x * 8 + (threadIdx.x >> 5);   // query id (bh*2048 + l)
    int lane = threadIdx.x & 31;
    int bh = w >> 11;
    int l  = w & (Lq - 1);
    float2 q = ((const float2*)(Q + (size_t)w * Dq))[lane];
    const float* Kb = K + (size_t)bh * Lq * Dq;
    int e0 = idxs[l * SK + lane];
    int e1 = (lane < 8) ? idxs[l * SK + 32 + lane] : 0;

    float a = dot16(Kb, q, e0, 0, lane);
    float b = dot16(Kb, q, e0, 16, lane);
    float c = dot8(Kb, q, e1, lane);

    float mx = fmaxf(fmaxf(a, b), c);
    float sm = 0.5f * (a + b) + 0.25f * c;
    #pragma unroll
    for (int o = 16; o; o >>= 1) {
        mx = fmaxf(mx, __shfl_xor_sync(0xffffffffu, mx, o));
        sm += __shfl_xor_sync(0xffffffffu, sm, o);
    }
    if (lane == 0) g_M[w] = mx - sm * (1.0f / (float)Lq);
}

// ---------------- kernel 2: top-40 per (b,h), 4-level radix select -------
__global__ void k_topk() {
    __shared__ int hist[8][256];
    __shared__ int suf[257];
    __shared__ int wred[8];
    __shared__ int s_T, s_cnt, s_min;
    int bh = blockIdx.x;
    int t = threadIdx.x, lane = t & 31, w = t >> 5;

    unsigned key[8];
    #pragma unroll
    for (int j = 0; j < 8; j++) {
        unsigned u = __float_as_uint(g_M[bh * Lq + t * 8 + j]);
        key[j] = (u & 0x80000000u) ? ~u : (u | 0x80000000u);
    }
    unsigned prefix = 0;
    int need = NT;
    if (t == 0) s_cnt = 0;

    #pragma unroll
    for (int level = 0; level < 4; level++) {
        int shift = 24 - 8 * level;
        for (int b = t; b < 8 * 256; b += 256) (&hist[0][0])[b] = 0;
        __syncthreads();
        #pragma unroll
        for (int j = 0; j < 8; j++) {
            bool match = (level == 0) || ((key[j] >> (shift + 8)) == prefix);
            if (match) atomicAdd(&hist[w][(key[j] >> shift) & 255u], 1);
        }
        __syncthreads();
        int h = 0;
        #pragma unroll
        for (int ww = 0; ww < 8; ww++) h += hist[ww][t];
        int sv = h;
        #pragma unroll
        for (int off = 1; off < 32; off <<= 1) {
            int v = __shfl_down_sync(0xffffffffu, sv, off);
            if (lane + off < 32) sv += v;
        }
        int wtot = __shfl_sync(0xffffffffu, sv, 0);
        if (lane == 0) wred[w] = wtot;
        __syncthreads();
        int higher = 0;
        #pragma unroll
        for (int ww = 0; ww < 8; ww++) if (ww > w) higher += wred[ww];
        suf[t] = sv + higher;
        if (t == 0) suf[256] = 0;
        __syncthreads();
        if (suf[t] >= need && suf[t + 1] < need) s_T = t;
        __syncthreads();
        int T = s_T;
        #pragma unroll
        for (int j = 0; j < 8; j++) {
            bool match = (level == 0) || ((key[j] >> (shift + 8)) == prefix);
            if (match && (int)((key[j] >> shift) & 255u) > T) {
                int p = atomicAdd(&s_cnt, 1);
                g_top[bh * NT + p] = t * 8 + j;
            }
        }
        need -= suf[T + 1];
        prefix = (prefix << 8) | (unsigned)T;
        __syncthreads();
    }

    for (int it = 0; it < need; it++) {
        int mi = Lq;
        #pragma unroll
        for (int j = 0; j < 8; j++)
            if (key[j] == prefix) mi = min(mi, t * 8 + j);
        #pragma unroll
        for (int off = 16; off; off >>= 1)
            mi = min(mi, __shfl_xor_sync(0xffffffffu, mi, off));
        if (lane == 0) wred[w] = mi;
        __syncthreads();
        if (t == 0) {
            int m = wred[0];
            #pragma unroll
            for (int ww = 1; ww < 8; ww++) m = min(m, wred[ww]);
            s_min = m;
            g_top[bh * NT + (NT - need) + it] = m;
        }
        __syncthreads();
        int m = s_min;
        if (m >= t * 8 && m < t * 8 + 8) key[m - t * 8] = 0u;
        __syncthreads();
    }
}

// ---------------- kernel 3: compact scaled Q_top --------------------------
// g_qtop[bh][u][d] = Q[bh][top[u]][d] * SCALE  (scale exact: 2^-3)
__global__ void k_gatherq(const float* __restrict__ Q) {
    int i = blockIdx.x * 256 + threadIdx.x;    // BH*NT*Dq = 81920
    int d = i & 63;
    int u = (i >> 6) % NT;
    int bh = (i >> 6) / NT;
    int qi = g_top[bh * NT + u];
    g_qtop[i] = Q[((size_t)bh * Lq + qi) * Dq + d] * SCALE;
}

// ---------------- kernel 4: V mean over L per (b,h), float4 --------------
__global__ void k_vmean(const float* __restrict__ V) {
    __shared__ float4 ps[256];
    int bh = blockIdx.x;
    int t = threadIdx.x;
    int d4 = t & 15, part = t >> 4;
    const float4* Vb = (const float4*)(V + (size_t)bh * Lq * Dq);
    float4 s = make_float4(0.f, 0.f, 0.f, 0.f);
    int k0 = part * 128;
    for (int k = k0; k < k0 + 128; k++) {
        float4 v = Vb[(size_t)k * 16 + d4];
        s.x += v.x; s.y += v.y; s.z += v.z; s.w += v.w;
    }
    ps[t] = s;
    __syncthreads();
    if (t < 16) {
        float4 a = ps[t];
        #pragma unroll
        for (int pI = 1; pI < 16; pI++) {
            float4 v = ps[pI * 16 + t];
            a.x += v.x; a.y += v.y; a.z += v.z; a.w += v.w;
        }
        const float inv = 1.0f / (float)Lq;
        a.x *= inv; a.y *= inv; a.z *= inv; a.w *= inv;
        ((float4*)g_vmean)[bh * 16 + t] = a;
    }
}

// ---------------- kernel 5: broadcast V_mean (4 stores/thread) -----------
__global__ void k_fill(float4* __restrict__ out4) {
    int base = blockIdx.x * 1024 + threadIdx.x;   // 1024 blocks x 256 thr x 4
    #pragma unroll
    for (int r = 0; r < 4; r++) {
        int i = base + r * 256;
        out4[i] = ((const float4*)g_vmean)[(((i >> 15)) << 4) | (i & 15)];
    }
}

// ---------------- kernel 6: scores = Q_top(scaled) @ K^T -----------------
// 64-key tiles -> grid BH*32 = 1024 blocks, 256 threads. Q from compact
// g_qtop (coalesced float4). Warp = 5 queries; lane = 2 keys (float2).
__global__ void k_scores(const float* __restrict__ K) {
    __shared__ float qs[NT * Dq];           // 10 KB
    __shared__ float Kt[Dq * 66];           // transposed [d][k], pad 66
    int bh = blockIdx.x >> 5;
    int kt = blockIdx.x & 31;
    int t = threadIdx.x;                    // 256
    const float* Kb = K + (size_t)bh * Lq * Dq;
    {   // coalesced Q stage (640 float4s)
        float4* q4 = (float4*)qs;
        const float4* g4 = (const float4*)(g_qtop + bh * NT * Dq);
        #pragma unroll
        for (int j = t; j < NT * Dq / 4; j += 256) q4[j] = g4[j];
    }
    for (int j = t; j < 64 * Dq; j += 256) {
        int r = j >> 6, d = j & 63;
        Kt[d * 66 + r] = Kb[(size_t)(kt * 64 + r) * Dq + d];
    }
    __syncthreads();
    int w = t >> 5, lane = t & 31;          // warp w: queries w*5..w*5+4
    float acc[5][2] = {};
    #pragma unroll
    for (int dc = 0; dc < Dq; dc += 4) {
        float4 a[5];
        #pragma unroll
        for (int i = 0; i < 5; i++)
            a[i] = *(const float4*)&qs[(w * 5 + i) * Dq + dc];
        #pragma unroll
        for (int j = 0; j < 4; j++) {
            float2 b = *(const float2*)&Kt[(dc + j) * 66 + lane * 2];
            #pragma unroll
            for (int i = 0; i < 5; i++) {
                float aj = (j == 0) ? a[i].x : (j == 1) ? a[i].y : (j == 2) ? a[i].z : a[i].w;
                acc[i][0] = fmaf(aj, b.x, acc[i][0]);
                acc[i][1] = fmaf(aj, b.y, acc[i][1]);
            }
        }
    }
    #pragma unroll
    for (int i = 0; i < 5; i++) {
        int u = w * 5 + i;
        *(float2*)&g_scores[((size_t)(bh * NT + u)) * Lq + kt * 64 + lane * 2]
            = make_float2(acc[i][0], acc[i][1]);
    }
}

// ---------------- kernel 7: softmax 2-pass, float4 + FMA-pipe exp --------
__global__ void k_softmax() {
    __shared__ float red[8];
    int row = blockIdx.x;                  // BH*NT = 1280 rows
    float4* s4 = (float4*)(g_scores + (size_t)row * Lq);
    int t = threadIdx.x, lane = t & 31, wid = t >> 5;
    float4 v0 = s4[t * 2], v1 = s4[t * 2 + 1];
    float mx = fmaxf(fmaxf(fmaxf(v0.x, v0.y), fmaxf(v0.z, v0.w)),
                     fmaxf(fmaxf(v1.x, v1.y), fmaxf(v1.z, v1.w)));
    #pragma unroll
    for (int o = 16; o; o >>= 1) mx = fmaxf(mx, __shfl_xor_sync(0xffffffffu, mx, o));
    if (lane == 0) red[wid] = mx;
    __syncthreads();
    mx = red[0];
    #pragma unroll
    for (int i = 1; i < 8; i++) mx = fmaxf(mx, red[i]);
    v0.x = fexpf(v0.x - mx); v0.y = fexpf(v0.y - mx);
    v0.z = fexpf(v0.z - mx); v0.w = fexpf(v0.w - mx);
    v1.x = fexpf(v1.x - mx); v1.y = fexpf(v1.y - mx);
    v1.z = fexpf(v1.z - mx); v1.w = fexpf(v1.w - mx);
    s4[t * 2] = v0; s4[t * 2 + 1] = v1;
    float sum = (v0.x + v0.y + v0.z + v0.w) + (v1.x + v1.y + v1.z + v1.w);
    #pragma unroll
    for (int o = 16; o; o >>= 1) sum += __shfl_xor_sync(0xffffffffu, sum, o);
    __syncthreads();
    if (lane == 0) red[wid] = sum;
    __syncthreads();
    if (t == 0) {
        sum = 0.f;
        #pragma unroll
        for (int i = 0; i < 8; i++) sum += red[i];
        g_inv[row] = 1.0f / sum;
    }
}

// ---------------- kernel 8: ctx partial = exp_scores @ V (k-split) -------
__global__ void k_ctx(const float* __restrict__ V) {
    __shared__ float Vs[128 * Dq];          // 32 KB
    int bh = blockIdx.x >> 3;
    int ks = blockIdx.x & 7;
    int t = threadIdx.x;
    int tu = t >> 5;
    int td = t & 31;
    const float* Vb = V + (size_t)bh * Lq * Dq;
    const float* Sb = g_scores + (size_t)bh * NT * Lq;
    float acc[5][2] = {};
    for (int sub = 0; sub < 2; sub++) {
        int k0 = ks * 256 + sub * 128;
        __syncthreads();
        for (int j = t; j < 128 * Dq; j += 256) Vs[j] = Vb[(size_t)k0 * Dq + j];
        __syncthreads();
        #pragma unroll 2
        for (int kk = 0; kk < 128; kk += 4) {
            float4 a[5];
            #pragma unroll
            for (int i = 0; i < 5; i++)
                a[i] = *(const float4*)&Sb[(size_t)(tu * 5 + i) * Lq + k0 + kk];
            #pragma unroll
            for (int j = 0; j < 4; j++) {
                float2 v = *(const float2*)&Vs[(kk + j) * Dq + td * 2];
                #pragma unroll
                for (int i = 0; i < 5; i++) {
                    float aj = (j == 0) ? a[i].x : (j == 1) ? a[i].y : (j == 2) ? a[i].z : a[i].w;
                    acc[i][0] = fmaf(aj, v.x, acc[i][0]);
                    acc[i][1] = fmaf(aj, v.y, acc[i][1]);
                }
            }
        }
    }
    #pragma unroll
    for (int i = 0; i < 5; i++) {
        int u = tu * 5 + i;
        *(float2*)&g_part[(((size_t)ks * BH + bh) * NT + u) * Dq + td * 2]
            = make_float2(acc[i][0], acc[i][1]);
    }
}

// ---------------- kernel 9: sum partials * inv_sum, scatter --------------
__global__ void k_scatter(float* __restrict__ out) {
    int i = blockIdx.x * blockDim.x + threadIdx.x;   // BH*NT*D = 81920
    if (i >= BH * NT * Dq) return;
    int d = i & 63;
    int u = (i >> 6) % NT;
    int bh = (i >> 6) / NT;
    float s = 0.f;
    #pragma unroll
    for (int ks = 0; ks < 8; ks++)
        s += g_part[(((size_t)ks * BH + bh) * NT + u) * Dq + d];
    s *= g_inv[bh * NT + u];
    int qi = g_top[bh * NT + u];
    out[((size_t)bh * Lq + qi) * Dq + d] = s;
}

// ---------------- launch ---------------------------------------------------
extern "C" void kernel_launch(void* const* d_in, const int* in_sizes, int n_in,
                              void* d_out, int out_size) {
    const float* Q = (const float*)d_in[0];
    const float* K = (const float*)d_in[1];
    const float* V = (const float*)d_in[2];
    const int* idxs = (const int*)d_in[3];
    float* out = (float*)d_out;

    // order: k_scores (compact-Q, 1024-block version) is user launch #4.
    k_M<<<(BH * Lq) / 8, 256>>>(Q, K, idxs);                  // 1
    k_topk<<<BH, 256>>>();                                    // 2
    k_gatherq<<<(BH * NT * Dq) / 256, 256>>>(Q);              // 3
    k_scores<<<BH * 32, 256>>>(K);                            // 4  <-- profiled
    k_vmean<<<BH, 256>>>(V);                                  // 5
    k_fill<<<(BH * Lq * Dq / 4) / 1024, 256>>>((float4*)out); // 6
    k_softmax<<<BH * NT, 256>>>();                            // 7
    k_ctx<<<BH * 8, 256>>>(V);                                // 8
    k_scatter<<<(BH * NT * Dq + 255) / 256, 256>>>(out);      // 9
}